// round 15
// baseline (speedup 1.0000x reference)
#include <cuda_runtime.h>
#include <cuda_fp16.h>
#include <cstdint>

// Shapes: x:[8,4096,1024]f32, theta:[8], w1:[4096,8], b1:[4096], w2:[1024,4096], b2:[1024]
// out:[8,4096,1024] f32
#define M_TOK 32768
#define E_DIM 1024
#define F_DIM 4096
#define NQ 8

#if defined(__CUDA_ARCH_FEAT_SM103_ALL) || defined(__CUDA_ARCH_FEAT_SM100_ALL) || !defined(__CUDA_ARCH__)
#define HAS_BLACKWELL 1
#else
#define HAS_BLACKWELL 0
#endif

// Tiled + SW64-swizzled layouts (64B rows, Swizzle<2,4,3>):
//   g_H  : tile (mb, kt) = 128 rows x 32 halves = 8KB  at ((mb*128 + kt) << 13), mb = token>>7
//   g_w2h: tile (nb, kt) = 512 rows x 32 halves = 32KB at ((nb*128 + kt) << 15), nb = e>>9
// within tile, 16B chunk c (0..3) of row r: soff = r*64 + ((c ^ ((r>>1)&3)) << 4)
__device__ __half g_H[(size_t)M_TOK * F_DIM];     // 256 MiB
__device__ __half g_w2h[(size_t)E_DIM * F_DIM];   // 8 MiB

// ===========================================================================
// PTX helpers
// ===========================================================================
__device__ __forceinline__ uint32_t smem_u32(const void* p) {
    uint32_t a;
    asm("{ .reg .u64 t; cvta.to.shared.u64 t, %1; cvt.u32.u64 %0, t; }" : "=r"(a) : "l"(p));
    return a;
}

#define MBAR_INIT(addr, cnt) \
    asm volatile("mbarrier.init.shared.b64 [%0], %1;" :: "r"(addr), "r"(cnt) : "memory")

#define MBAR_WAIT(addr, parity) do { \
    uint32_t _mb = (addr); uint32_t _p = (parity); uint32_t _done; \
    asm volatile("{\n\t.reg .pred p;\n\t" \
        "mbarrier.try_wait.parity.acquire.cta.shared::cta.b64 p, [%1], %2;\n\t" \
        "selp.b32 %0, 1, 0, p;\n\t}" : "=r"(_done) : "r"(_mb), "r"(_p) : "memory"); \
    if (!_done) { \
        asm volatile("{\n\t.reg .pred P1;\n\t" \
            "WL_%=:\n\t" \
            "mbarrier.try_wait.parity.acquire.cta.shared::cta.b64 P1, [%0], %1, 0x989680;\n\t" \
            "@P1 bra.uni WD_%=;\n\t" \
            "bra.uni WL_%=;\n\t" \
            "WD_%=:\n\t}" :: "r"(_mb), "r"(_p) : "memory"); \
    } \
} while (0)

#define MBAR_EXPECT_TX(addr, bytes) \
    asm volatile("mbarrier.arrive.expect_tx.shared.b64 _, [%0], %1;" \
                 :: "r"(addr), "r"(bytes) : "memory")

#if HAS_BLACKWELL && defined(__CUDA_ARCH__)
__device__ __forceinline__ uint32_t elect_one() {
    uint32_t pred;
    asm volatile("{\n\t.reg .pred p;\n\telect.sync _|p, 0xFFFFFFFF;\n\tselp.b32 %0, 1, 0, p;\n\t}" : "=r"(pred));
    return pred;
}
__device__ __forceinline__ uint32_t cluster_cx() {
    uint32_t r;
    asm("mov.u32 %0, %%cluster_ctaid.x;" : "=r"(r));
    return r;
}
__device__ __forceinline__ uint32_t cluster_cy() {
    uint32_t r;
    asm("mov.u32 %0, %%cluster_ctaid.y;" : "=r"(r));
    return r;
}

#define BULK_G2S_MC(dst, src, bytes, mbar, mask) \
    asm volatile("cp.async.bulk.shared::cluster.global.mbarrier::complete_tx::bytes.multicast::cluster [%0], [%1], %2, [%3], %4;" \
        :: "r"(dst), "l"(src), "r"(bytes), "r"(mbar), "h"((unsigned short)(mask)) : "memory")

#define COMMIT_MC(mbar, mask) \
    asm volatile("tcgen05.commit.cta_group::1.mbarrier::arrive::one.shared::cluster.multicast::cluster.b64 [%0], %1;" \
        :: "r"(mbar), "h"((unsigned short)(mask)) : "memory")
#define COMMIT_LOCAL(mbar) \
    asm volatile("tcgen05.commit.cta_group::1.mbarrier::arrive::one.shared::cluster.b64 [%0];" \
        :: "r"(mbar) : "memory")

__device__ __forceinline__ void mma_f16_ss(uint32_t d_tmem, uint64_t a_desc, uint64_t b_desc,
                                           uint32_t idesc, uint32_t enable) {
    asm volatile(
        "{\n\t.reg .pred p;\n\t"
        "setp.ne.u32 p, %4, 0;\n\t"
        "tcgen05.mma.cta_group::1.kind::f16 [%0], %1, %2, %3, {%5, %5, %5, %5}, p;\n\t}"
        :: "r"(d_tmem), "l"(a_desc), "l"(b_desc), "r"(idesc), "r"(enable), "r"(0u)
        : "memory");
}

__device__ __forceinline__ void fma2(unsigned long long& d, unsigned long long a,
                                     unsigned long long b) {
    asm("fma.rn.f32x2 %0, %1, %2, %0;" : "+l"(d) : "l"(a), "l"(b));
}
__device__ __forceinline__ unsigned long long pack2(float lo, float hi) {
    unsigned long long o;
    asm("mov.b64 %0, {%1, %2};" : "=l"(o) : "f"(lo), "f"(hi));
    return o;
}
__device__ __forceinline__ void unpack2(float& lo, float& hi, unsigned long long v) {
    asm("mov.b64 {%0, %1}, %2;" : "=f"(lo), "=f"(hi) : "l"(v));
}
#endif

#define TCGEN05_LD_X32(r, addr) \
    asm volatile("tcgen05.ld.sync.aligned.32x32b.x32.b32 " \
        "{%0, %1, %2, %3, %4, %5, %6, %7, " \
        " %8, %9, %10, %11, %12, %13, %14, %15, " \
        " %16, %17, %18, %19, %20, %21, %22, %23, " \
        " %24, %25, %26, %27, %28, %29, %30, %31}, [%32];" \
        : "=r"((r)[0]),  "=r"((r)[1]),  "=r"((r)[2]),  "=r"((r)[3]), \
          "=r"((r)[4]),  "=r"((r)[5]),  "=r"((r)[6]),  "=r"((r)[7]), \
          "=r"((r)[8]),  "=r"((r)[9]),  "=r"((r)[10]), "=r"((r)[11]), \
          "=r"((r)[12]), "=r"((r)[13]), "=r"((r)[14]), "=r"((r)[15]), \
          "=r"((r)[16]), "=r"((r)[17]), "=r"((r)[18]), "=r"((r)[19]), \
          "=r"((r)[20]), "=r"((r)[21]), "=r"((r)[22]), "=r"((r)[23]), \
          "=r"((r)[24]), "=r"((r)[25]), "=r"((r)[26]), "=r"((r)[27]), \
          "=r"((r)[28]), "=r"((r)[29]), "=r"((r)[30]), "=r"((r)[31]) \
        : "r"(addr))

// SW64 K-major smem descriptor: layout=4, version=1, SBO=32, LBO=1
static constexpr uint64_t DESC_BASE_SW64 =
    (uint64_t(4) << 61) | (uint64_t(1) << 46) | (uint64_t(32) << 32) | (uint64_t(1) << 16);
__device__ __forceinline__ uint64_t make_desc64(uint32_t addr) {
    return DESC_BASE_SW64 | (uint64_t)((addr >> 4) & 0x3FFF);
}

// ===========================================================================
// Kernel 1: H = relu(q @ w1^T + b1), fp16, tiled SW64.
// (byte-identical to the proven 67.6us R8/R11/R14 version)
// ===========================================================================
__global__ __launch_bounds__(256) void compute_h_kernel(
    const float* __restrict__ x, const float* __restrict__ theta,
    const float* __restrict__ w1, const float* __restrict__ b1)
{
    __shared__ float sq[64 * NQ];
    const int tid = threadIdx.x;
    const int hch = blockIdx.x * 256 + tid;    // 0..1023
    const int kt  = hch >> 3;                  // 0..127
    const int q   = hch & 7;
    const int c16 = q >> 1;
    const int hh  = q & 1;
    const int f0  = kt * 32 + q * 4;
    const int ty0 = blockIdx.y * 64;

    for (int idx = tid; idx < 64 * NQ; idx += 256) {
        int t = idx >> 3, i = idx & 7;
        sq[idx] = cosf(x[(size_t)(ty0 + t) * E_DIM + i]);
    }

    float ct[NQ];
#pragma unroll
    for (int i = 0; i < NQ; i++) ct[i] = cosf(theta[i]);

    const int mb = ty0 >> 7;
    const int r0 = ty0 & 127;
    char* tbase = (char*)g_H + (((size_t)(mb * 128 + kt)) << 13) + (size_t)r0 * 64 + hh * 8;

#if HAS_BLACKWELL && defined(__CUDA_ARCH__)
    unsigned long long wp[NQ][2];
#pragma unroll
    for (int j = 0; j < 2; j++) {
        const float* rr0 = w1 + (size_t)(f0 + 2 * j) * NQ;
        const float* rr1 = rr0 + NQ;
        float4 a0 = *(const float4*)(rr0);
        float4 a1 = *(const float4*)(rr0 + 4);
        float4 c0 = *(const float4*)(rr1);
        float4 c1 = *(const float4*)(rr1 + 4);
        wp[0][j] = pack2(a0.x * ct[0], c0.x * ct[0]);
        wp[1][j] = pack2(a0.y * ct[1], c0.y * ct[1]);
        wp[2][j] = pack2(a0.z * ct[2], c0.z * ct[2]);
        wp[3][j] = pack2(a0.w * ct[3], c0.w * ct[3]);
        wp[4][j] = pack2(a1.x * ct[4], c1.x * ct[4]);
        wp[5][j] = pack2(a1.y * ct[5], c1.y * ct[5]);
        wp[6][j] = pack2(a1.z * ct[6], c1.z * ct[6]);
        wp[7][j] = pack2(a1.w * ct[7], c1.w * ct[7]);
    }
    unsigned long long bb[2];
#pragma unroll
    for (int j = 0; j < 2; j++) bb[j] = pack2(b1[f0 + 2 * j], b1[f0 + 2 * j + 1]);

    __syncthreads();

#pragma unroll 8
    for (int n = 0; n < 64; n++) {
        unsigned long long acc[2] = { bb[0], bb[1] };
#pragma unroll
        for (int i = 0; i < NQ; i++) {
            float qv = sq[n * NQ + i];
            unsigned long long q2 = pack2(qv, qv);
            fma2(acc[0], q2, wp[i][0]);
            fma2(acc[1], q2, wp[i][1]);
        }
        uint2 vals;
        {
            float lo, hi;
            unpack2(lo, hi, acc[0]);
            __half2 h2 = __floats2half2_rn(fmaxf(lo, 0.f), fmaxf(hi, 0.f));
            vals.x = *(uint32_t*)&h2;
            unpack2(lo, hi, acc[1]);
            h2 = __floats2half2_rn(fmaxf(lo, 0.f), fmaxf(hi, 0.f));
            vals.y = *(uint32_t*)&h2;
        }
        uint32_t sw = (uint32_t)((c16 ^ ((n >> 1) & 3)) << 4) - (uint32_t)(c16 << 4);
        *(uint2*)(tbase + (size_t)n * 64 + (int)sw + c16 * 16) = vals;
    }
#else
    float w[4][NQ], bbs[4];
#pragma unroll
    for (int fp = 0; fp < 4; fp++) {
#pragma unroll
        for (int i = 0; i < NQ; i++) w[fp][i] = w1[(size_t)(f0 + fp) * NQ + i] * ct[i];
        bbs[fp] = b1[f0 + fp];
    }
    __syncthreads();
    for (int n = 0; n < 64; n++) {
        __half hv[4];
#pragma unroll
        for (int fp = 0; fp < 4; fp++) {
            float acc = bbs[fp];
#pragma unroll
            for (int i = 0; i < NQ; i++) acc = fmaf(sq[n * NQ + i], w[fp][i], acc);
            hv[fp] = __float2half(fmaxf(acc, 0.f));
        }
        uint32_t swoff = (uint32_t)((c16 ^ ((n >> 1) & 3)) << 4);
        *(uint2*)(tbase + (size_t)n * 64 + swoff) = *(uint2*)hv;
    }
#endif
}

// ===========================================================================
// Kernel 2: w2 f32 -> f16, tiled SW64 (512-row tiles) — unchanged
// ===========================================================================
__global__ __launch_bounds__(256) void convert_w2_kernel(const float* __restrict__ w2)
{
    int idx = blockIdx.x * 256 + threadIdx.x;
    int c  = idx & 3;
    int r  = (idx >> 2) & 511;
    int kt = (idx >> 11) & 127;
    int nb = idx >> 18;

    const float* src = w2 + ((size_t)(nb * 512 + r)) * F_DIM + kt * 32 + c * 8;
    float4 v0 = *(const float4*)(src);
    float4 v1 = *(const float4*)(src + 4);
    __half2 h0 = __floats2half2_rn(v0.x, v0.y);
    __half2 h1 = __floats2half2_rn(v0.z, v0.w);
    __half2 h2 = __floats2half2_rn(v1.x, v1.y);
    __half2 h3 = __floats2half2_rn(v1.z, v1.w);
    uint4 out;
    out.x = *(uint32_t*)&h0; out.y = *(uint32_t*)&h1;
    out.z = *(uint32_t*)&h2; out.w = *(uint32_t*)&h3;

    size_t off = (((size_t)nb * 128 + kt) << 15) + (size_t)r * 64
               + (uint32_t)((c ^ ((r >> 1) & 3)) << 4);
    *(uint4*)((char*)g_w2h + off) = out;
}

// ===========================================================================
// Kernel 3: tcgen05 GEMM at occupancy 2, BM=128, BN=256, KC=32, 4-stage ring.
// (2,2,1) cluster: x-pair (same m-block? no — same cy shares A) —
//   CTAs with equal cluster_ctaid.y share A (same blockIdx.y): 2-way A multicast,
//   CTAs with equal cluster_ctaid.x share B (same blockIdx.x): 2-way B multicast.
// free[s] count=4, armed by COMMIT_MC(0xF) from every cluster CTA.
// Fill traffic: A 0.5GB + B 0.5GB = 1.0GB (below LTS cap) -> MMA-bound.
// ===========================================================================
#define BM 128
#define BN 256
#define KC 32
#define NKT (F_DIM / KC)              // 128
#define A_TILE 8192
#define B_TILE 16384
#define STAGE_BYTES (A_TILE + B_TILE) // 24576
#define NSTAGE 4
#define SMEM_DATA 1024
#define GEMM_SMEM (SMEM_DATA + NSTAGE * STAGE_BYTES)   // 99328
#define TMEM_COLS 256

__global__ __launch_bounds__(256, 2) __cluster_dims__(2, 2, 1)
void gemm_tc_kernel(float* __restrict__ out, const float* __restrict__ b2)
{
#if HAS_BLACKWELL && defined(__CUDA_ARCH__)
    extern __shared__ char smem[];
    const uint32_t sbase = smem_u32(smem);
    const int tid  = threadIdx.x;
    const int warp = tid >> 5;
    const int lane = tid & 31;
    const int nb = blockIdx.x;        // 0..3
    const int n0 = nb * BN;
    const int m0 = blockIdx.y * BM;
    const uint32_t cx = cluster_cx(); // 0/1
    const uint32_t cy = cluster_cy(); // 0/1
    // rank = cx + 2*cy (x fastest)
    const uint16_t maskA = (uint16_t)(0x3u << (2 * cy));           // x-pair at my cy
    const uint16_t maskB = (uint16_t)((1u << cx) | (1u << (cx + 2))); // y-pair at my cx

    const uint32_t mb_full0 = sbase + 8;    // full[4]: +8..+39
    const uint32_t mb_free0 = sbase + 48;   // free[4]: +48..+79
    const uint32_t mb_done  = sbase + 88;

    if (warp == 0) {
        asm volatile("tcgen05.alloc.cta_group::1.sync.aligned.shared::cta.b32 [%0], %1;"
                     :: "r"(sbase), "r"((uint32_t)TMEM_COLS) : "memory");
    }
    __syncthreads();
    uint32_t tmem;
    asm volatile("ld.shared.b32 %0, [%1];" : "=r"(tmem) : "r"(sbase));
    if (warp == 0)
        asm volatile("tcgen05.relinquish_alloc_permit.cta_group::1.sync.aligned;");

    if (tid == 0) {
#pragma unroll
        for (int s = 0; s < NSTAGE; s++) {
            MBAR_INIT(mb_full0 + s * 8, 1);
            MBAR_INIT(mb_free0 + s * 8, 4);   // multicast commit from all 4 cluster CTAs
        }
        MBAR_INIT(mb_done, 1);
    }
    __syncthreads();
    asm volatile("barrier.cluster.arrive.aligned;" ::: "memory");
    asm volatile("barrier.cluster.wait.aligned;"   ::: "memory");

    const char* Abase = (const char*)g_H + ((size_t)blockIdx.y * 128) * A_TILE;
    // B rows [nb*256, nb*256+255]: 512-row tile (nb>>1, kt), block (nb&1)*16384.
    const char* Bbase = (const char*)g_w2h + (((size_t)(nb >> 1) * 128) << 15)
                      + (size_t)(nb & 1) * 16384;
    const uint32_t idesc = (1u << 4) | ((BN / 8) << 17) | (8u << 24);  // F32 acc, N=256, M=128

    if (tid == 0) {
        // ---- producer: cooperative 2-way A slice + 2-way B slice ----
        for (int kn = 0; kn < NKT; kn++) {
            const int s = kn % NSTAGE;
            const int r = kn / NSTAGE;
            if (r >= 1) MBAR_WAIT(mb_free0 + s * 8, (r - 1) & 1);
            const uint32_t mb = mb_full0 + s * 8;
            const uint32_t sa = sbase + SMEM_DATA + s * STAGE_BYTES;
            const uint32_t sb = sa + A_TILE;
            MBAR_EXPECT_TX(mb, (uint32_t)STAGE_BYTES);  // 2x4K A slices + 2x8K B slices
            BULK_G2S_MC(sa + cx * 4096,
                        Abase + (size_t)kn * A_TILE + cx * 4096,
                        4096, mb, maskA);
            BULK_G2S_MC(sb + cy * 8192,
                        Bbase + ((size_t)kn << 15) + cy * 8192,
                        8192, mb, maskB);
        }
    } else if (warp == 1) {
        // ---- MMA issuer ----
        if (elect_one()) {
            for (int kt = 0; kt < NKT; kt++) {
                const int s = kt % NSTAGE;
                const int r = kt / NSTAGE;
                MBAR_WAIT(mb_full0 + s * 8, r & 1);
                const uint32_t sa = sbase + SMEM_DATA + s * STAGE_BYTES;
                const uint64_t adesc = make_desc64(sa);
                const uint64_t bdesc = make_desc64(sa + A_TILE);
#pragma unroll
                for (int k2 = 0; k2 < 2; k2++) {
                    mma_f16_ss(tmem, adesc + k2 * 2, bdesc + k2 * 2,
                               idesc, (kt > 0 || k2 > 0) ? 1u : 0u);
                }
                COMMIT_MC(mb_free0 + s * 8, 0xF);
            }
            COMMIT_LOCAL(mb_done);
        }
    }

    MBAR_WAIT(mb_done, 0);
    asm volatile("tcgen05.fence::after_thread_sync;" ::: "memory");

    // Epilogue: warp w covers rows (w&3)*32.., cols (w>>2)*128 + 0..127. Bias fused.
    {
        const int ch = warp >> 2;   // column half 0/1
        const uint32_t dbase = tmem + ch * 128;
        const size_t row = (size_t)(m0 + (warp & 3) * 32 + lane);
        float4* dst = (float4*)(out + row * E_DIM + n0 + ch * 128);
        const float* bp = b2 + n0 + ch * 128;
#pragma unroll
        for (int c0 = 0; c0 < 128; c0 += 32) {
            uint32_t r[32];
            TCGEN05_LD_X32(r, dbase + c0);
            asm volatile("tcgen05.wait::ld.sync.aligned;" ::: "memory");
#pragma unroll
            for (int q = 0; q < 8; q++) {
                float4 v;
                v.x = __uint_as_float(r[4 * q + 0]) + __ldg(bp + c0 + 4 * q + 0);
                v.y = __uint_as_float(r[4 * q + 1]) + __ldg(bp + c0 + 4 * q + 1);
                v.z = __uint_as_float(r[4 * q + 2]) + __ldg(bp + c0 + 4 * q + 2);
                v.w = __uint_as_float(r[4 * q + 3]) + __ldg(bp + c0 + 4 * q + 3);
                dst[(c0 >> 2) + q] = v;
            }
        }
        asm volatile("tcgen05.fence::before_thread_sync;" ::: "memory");
    }

    __syncthreads();
    if (tid == 0) {
#pragma unroll
        for (int s = 0; s < NSTAGE; s++) {
            asm volatile("mbarrier.inval.shared.b64 [%0];" :: "r"(mb_full0 + s * 8) : "memory");
            asm volatile("mbarrier.inval.shared.b64 [%0];" :: "r"(mb_free0 + s * 8) : "memory");
        }
        asm volatile("mbarrier.inval.shared.b64 [%0];" :: "r"(mb_done) : "memory");
    }
    __syncthreads();
    if (warp == 0) {
        asm volatile("tcgen05.dealloc.cta_group::1.sync.aligned.b32 %0, %1;"
                     :: "r"(tmem), "r"((uint32_t)TMEM_COLS));
    }
    asm volatile("barrier.cluster.arrive.aligned;" ::: "memory");
    asm volatile("barrier.cluster.wait.aligned;"   ::: "memory");
#endif  // HAS_BLACKWELL
}

// ===========================================================================
extern "C" void kernel_launch(void* const* d_in, const int* in_sizes, int n_in,
                              void* d_out, int out_size)
{
    const float* x     = (const float*)d_in[0];
    const float* theta = (const float*)d_in[1];
    const float* w1    = (const float*)d_in[2];
    const float* b1    = (const float*)d_in[3];
    const float* w2    = (const float*)d_in[4];
    const float* b2    = (const float*)d_in[5];
    float* out = (float*)d_out;

    dim3 gh(4, M_TOK / 64);
    compute_h_kernel<<<gh, 256>>>(x, theta, w1, b1);

    convert_w2_kernel<<<(E_DIM * F_DIM / 8) / 256, 256>>>(w2);

    cudaFuncSetAttribute(gemm_tc_kernel, cudaFuncAttributeMaxDynamicSharedMemorySize, GEMM_SMEM);
    dim3 gg(E_DIM / BN, M_TOK / BM);
    gemm_tc_kernel<<<gg, 256, GEMM_SMEM>>>(out, b2);
}

// round 16
// speedup vs baseline: 1.0523x; 1.0523x over previous
#include <cuda_runtime.h>
#include <cuda_fp16.h>
#include <cstdint>

// Shapes: x:[8,4096,1024]f32, theta:[8], w1:[4096,8], b1:[4096], w2:[1024,4096], b2:[1024]
// out:[8,4096,1024] f32
#define M_TOK 32768
#define E_DIM 1024
#define F_DIM 4096
#define NQ 8

#if defined(__CUDA_ARCH_FEAT_SM103_ALL) || defined(__CUDA_ARCH_FEAT_SM100_ALL) || !defined(__CUDA_ARCH__)
#define HAS_BLACKWELL 1
#else
#define HAS_BLACKWELL 0
#endif

// Tiled + SW64-swizzled layouts (64B rows, Swizzle<2,4,3>):
//   g_H  : tile (mb, kt) = 128 rows x 32 halves = 8KB  at ((mb*128 + kt) << 13), mb = token>>7
//   g_w2h: tile (nb, kt) = 512 rows x 32 halves = 32KB at ((nb*128 + kt) << 15), nb = e>>9
// within tile, 16B chunk c (0..3) of row r: soff = r*64 + ((c ^ ((r>>1)&3)) << 4)
__device__ __half g_H[(size_t)M_TOK * F_DIM];     // 256 MiB
__device__ __half g_w2h[(size_t)E_DIM * F_DIM];   // 8 MiB

// ===========================================================================
// PTX helpers
// ===========================================================================
__device__ __forceinline__ uint32_t smem_u32(const void* p) {
    uint32_t a;
    asm("{ .reg .u64 t; cvta.to.shared.u64 t, %1; cvt.u32.u64 %0, t; }" : "=r"(a) : "l"(p));
    return a;
}

#define MBAR_INIT(addr, cnt) \
    asm volatile("mbarrier.init.shared.b64 [%0], %1;" :: "r"(addr), "r"(cnt) : "memory")

#define MBAR_WAIT(addr, parity) do { \
    uint32_t _mb = (addr); uint32_t _p = (parity); uint32_t _done; \
    asm volatile("{\n\t.reg .pred p;\n\t" \
        "mbarrier.try_wait.parity.acquire.cta.shared::cta.b64 p, [%1], %2;\n\t" \
        "selp.b32 %0, 1, 0, p;\n\t}" : "=r"(_done) : "r"(_mb), "r"(_p) : "memory"); \
    if (!_done) { \
        asm volatile("{\n\t.reg .pred P1;\n\t" \
            "WL_%=:\n\t" \
            "mbarrier.try_wait.parity.acquire.cta.shared::cta.b64 P1, [%0], %1, 0x989680;\n\t" \
            "@P1 bra.uni WD_%=;\n\t" \
            "bra.uni WL_%=;\n\t" \
            "WD_%=:\n\t}" :: "r"(_mb), "r"(_p) : "memory"); \
    } \
} while (0)

#define MBAR_EXPECT_TX(addr, bytes) \
    asm volatile("mbarrier.arrive.expect_tx.shared.b64 _, [%0], %1;" \
                 :: "r"(addr), "r"(bytes) : "memory")

#if HAS_BLACKWELL && defined(__CUDA_ARCH__)
__device__ __forceinline__ uint32_t elect_one() {
    uint32_t pred;
    asm volatile("{\n\t.reg .pred p;\n\telect.sync _|p, 0xFFFFFFFF;\n\tselp.b32 %0, 1, 0, p;\n\t}" : "=r"(pred));
    return pred;
}
__device__ __forceinline__ uint32_t ctarank() {
    uint32_t r;
    asm("mov.u32 %0, %%cluster_ctarank;" : "=r"(r));
    return r;
}

#define BULK_G2S(dst, src, bytes, mbar) \
    asm volatile("cp.async.bulk.shared::cluster.global.mbarrier::complete_tx::bytes [%0], [%1], %2, [%3];" \
        :: "r"(dst), "l"(src), "r"(bytes), "r"(mbar) : "memory")

#define BULK_G2S_MC(dst, src, bytes, mbar, mask) \
    asm volatile("cp.async.bulk.shared::cluster.global.mbarrier::complete_tx::bytes.multicast::cluster [%0], [%1], %2, [%3], %4;" \
        :: "r"(dst), "l"(src), "r"(bytes), "r"(mbar), "h"((unsigned short)(mask)) : "memory")

#define COMMIT_MC(mbar, mask) \
    asm volatile("tcgen05.commit.cta_group::1.mbarrier::arrive::one.shared::cluster.multicast::cluster.b64 [%0], %1;" \
        :: "r"(mbar), "h"((unsigned short)(mask)) : "memory")
#define COMMIT_LOCAL(mbar) \
    asm volatile("tcgen05.commit.cta_group::1.mbarrier::arrive::one.shared::cluster.b64 [%0];" \
        :: "r"(mbar) : "memory")

__device__ __forceinline__ void mma_f16_ss(uint32_t d_tmem, uint64_t a_desc, uint64_t b_desc,
                                           uint32_t idesc, uint32_t enable) {
    asm volatile(
        "{\n\t.reg .pred p;\n\t"
        "setp.ne.u32 p, %4, 0;\n\t"
        "tcgen05.mma.cta_group::1.kind::f16 [%0], %1, %2, %3, {%5, %5, %5, %5}, p;\n\t}"
        :: "r"(d_tmem), "l"(a_desc), "l"(b_desc), "r"(idesc), "r"(enable), "r"(0u)
        : "memory");
}

__device__ __forceinline__ void fma2(unsigned long long& d, unsigned long long a,
                                     unsigned long long b) {
    asm("fma.rn.f32x2 %0, %1, %2, %0;" : "+l"(d) : "l"(a), "l"(b));
}
__device__ __forceinline__ unsigned long long pack2(float lo, float hi) {
    unsigned long long o;
    asm("mov.b64 %0, {%1, %2};" : "=l"(o) : "f"(lo), "f"(hi));
    return o;
}
__device__ __forceinline__ void unpack2(float& lo, float& hi, unsigned long long v) {
    asm("mov.b64 {%0, %1}, %2;" : "=f"(lo), "=f"(hi) : "l"(v));
}
#endif

#define TCGEN05_LD_X32(r, addr) \
    asm volatile("tcgen05.ld.sync.aligned.32x32b.x32.b32 " \
        "{%0, %1, %2, %3, %4, %5, %6, %7, " \
        " %8, %9, %10, %11, %12, %13, %14, %15, " \
        " %16, %17, %18, %19, %20, %21, %22, %23, " \
        " %24, %25, %26, %27, %28, %29, %30, %31}, [%32];" \
        : "=r"((r)[0]),  "=r"((r)[1]),  "=r"((r)[2]),  "=r"((r)[3]), \
          "=r"((r)[4]),  "=r"((r)[5]),  "=r"((r)[6]),  "=r"((r)[7]), \
          "=r"((r)[8]),  "=r"((r)[9]),  "=r"((r)[10]), "=r"((r)[11]), \
          "=r"((r)[12]), "=r"((r)[13]), "=r"((r)[14]), "=r"((r)[15]), \
          "=r"((r)[16]), "=r"((r)[17]), "=r"((r)[18]), "=r"((r)[19]), \
          "=r"((r)[20]), "=r"((r)[21]), "=r"((r)[22]), "=r"((r)[23]), \
          "=r"((r)[24]), "=r"((r)[25]), "=r"((r)[26]), "=r"((r)[27]), \
          "=r"((r)[28]), "=r"((r)[29]), "=r"((r)[30]), "=r"((r)[31]) \
        : "r"(addr))

// SW64 K-major smem descriptor: layout=4, version=1, SBO=32, LBO=1
static constexpr uint64_t DESC_BASE_SW64 =
    (uint64_t(4) << 61) | (uint64_t(1) << 46) | (uint64_t(32) << 32) | (uint64_t(1) << 16);
__device__ __forceinline__ uint64_t make_desc64(uint32_t addr) {
    return DESC_BASE_SW64 | (uint64_t)((addr >> 4) & 0x3FFF);
}

// ===========================================================================
// Kernel 1 (MERGED): blocks 0..1023 compute H (128 tokens each, one full tile
// row span); blocks 1024..3071 convert w2 -> f16 tiled SW64.
// ===========================================================================
#define NBLK_H 1024
__global__ __launch_bounds__(256) void prep_kernel(
    const float* __restrict__ x, const float* __restrict__ theta,
    const float* __restrict__ w1, const float* __restrict__ b1,
    const float* __restrict__ w2)
{
    const int bid = blockIdx.x;
    const int tid = threadIdx.x;

    if (bid >= NBLK_H) {
        // ---------------- convert w2 ----------------
        int idx = (bid - NBLK_H) * 256 + tid;      // over E*F/8 16B chunks
        int c  = idx & 3;
        int r  = (idx >> 2) & 511;
        int kt = (idx >> 11) & 127;
        int nb = idx >> 18;

        const float* src = w2 + ((size_t)(nb * 512 + r)) * F_DIM + kt * 32 + c * 8;
        float4 v0 = *(const float4*)(src);
        float4 v1 = *(const float4*)(src + 4);
        __half2 h0 = __floats2half2_rn(v0.x, v0.y);
        __half2 h1 = __floats2half2_rn(v0.z, v0.w);
        __half2 h2 = __floats2half2_rn(v1.x, v1.y);
        __half2 h3 = __floats2half2_rn(v1.z, v1.w);
        uint4 outv;
        outv.x = *(uint32_t*)&h0; outv.y = *(uint32_t*)&h1;
        outv.z = *(uint32_t*)&h2; outv.w = *(uint32_t*)&h3;

        size_t off = (((size_t)nb * 128 + kt) << 15) + (size_t)r * 64
                   + (uint32_t)((c ^ ((r >> 1) & 3)) << 4);
        *(uint4*)((char*)g_w2h + off) = outv;
        return;
    }

    // ---------------- compute H: 128 tokens, exactly one tile-row (mb = by) ----------------
    __shared__ float sq[128 * NQ];
    const int bx = bid & 3;
    const int by = bid >> 2;                   // mb 0..255
    const int hch = bx * 256 + tid;            // 0..1023
    const int kt  = hch >> 3;                  // 0..127
    const int q   = hch & 7;
    const int c16 = q >> 1;
    const int hh  = q & 1;
    const int f0  = kt * 32 + q * 4;
    const int ty0 = by * 128;

    for (int idx = tid; idx < 128 * NQ; idx += 256) {
        int t = idx >> 3, i = idx & 7;
        sq[idx] = cosf(x[(size_t)(ty0 + t) * E_DIM + i]);
    }

    float ct[NQ];
#pragma unroll
    for (int i = 0; i < NQ; i++) ct[i] = cosf(theta[i]);

    char* tbase = (char*)g_H + (((size_t)(by * 128 + kt)) << 13) + hh * 8;

#if HAS_BLACKWELL && defined(__CUDA_ARCH__)
    unsigned long long wp[NQ][2];
#pragma unroll
    for (int j = 0; j < 2; j++) {
        const float* rr0 = w1 + (size_t)(f0 + 2 * j) * NQ;
        const float* rr1 = rr0 + NQ;
        float4 a0 = *(const float4*)(rr0);
        float4 a1 = *(const float4*)(rr0 + 4);
        float4 c0 = *(const float4*)(rr1);
        float4 c1 = *(const float4*)(rr1 + 4);
        wp[0][j] = pack2(a0.x * ct[0], c0.x * ct[0]);
        wp[1][j] = pack2(a0.y * ct[1], c0.y * ct[1]);
        wp[2][j] = pack2(a0.z * ct[2], c0.z * ct[2]);
        wp[3][j] = pack2(a0.w * ct[3], c0.w * ct[3]);
        wp[4][j] = pack2(a1.x * ct[4], c1.x * ct[4]);
        wp[5][j] = pack2(a1.y * ct[5], c1.y * ct[5]);
        wp[6][j] = pack2(a1.z * ct[6], c1.z * ct[6]);
        wp[7][j] = pack2(a1.w * ct[7], c1.w * ct[7]);
    }
    unsigned long long bb[2];
#pragma unroll
    for (int j = 0; j < 2; j++) bb[j] = pack2(b1[f0 + 2 * j], b1[f0 + 2 * j + 1]);

    __syncthreads();

#pragma unroll 8
    for (int n = 0; n < 128; n++) {
        unsigned long long acc[2] = { bb[0], bb[1] };
#pragma unroll
        for (int i = 0; i < NQ; i++) {
            float qv = sq[n * NQ + i];
            unsigned long long q2 = pack2(qv, qv);
            fma2(acc[0], q2, wp[i][0]);
            fma2(acc[1], q2, wp[i][1]);
        }
        uint2 vals;
        {
            float lo, hi;
            unpack2(lo, hi, acc[0]);
            __half2 h2 = __floats2half2_rn(fmaxf(lo, 0.f), fmaxf(hi, 0.f));
            vals.x = *(uint32_t*)&h2;
            unpack2(lo, hi, acc[1]);
            h2 = __floats2half2_rn(fmaxf(lo, 0.f), fmaxf(hi, 0.f));
            vals.y = *(uint32_t*)&h2;
        }
        uint32_t swoff = (uint32_t)((c16 ^ ((n >> 1) & 3)) << 4);
        *(uint2*)(tbase + (size_t)n * 64 + swoff) = vals;
    }
#else
    float w[4][NQ], bbs[4];
#pragma unroll
    for (int fp = 0; fp < 4; fp++) {
#pragma unroll
        for (int i = 0; i < NQ; i++) w[fp][i] = w1[(size_t)(f0 + fp) * NQ + i] * ct[i];
        bbs[fp] = b1[f0 + fp];
    }
    __syncthreads();
    for (int n = 0; n < 128; n++) {
        __half hv[4];
#pragma unroll
        for (int fp = 0; fp < 4; fp++) {
            float acc = bbs[fp];
#pragma unroll
            for (int i = 0; i < NQ; i++) acc = fmaf(sq[n * NQ + i], w[fp][i], acc);
            hv[fp] = __float2half(fmaxf(acc, 0.f));
        }
        uint32_t swoff = (uint32_t)((c16 ^ ((n >> 1) & 3)) << 4);
        *(uint2*)(tbase + (size_t)n * 64 + swoff) = *(uint2*)hv;
    }
#endif
}

// ===========================================================================
// Kernel 2: tcgen05 GEMM — byte-identical to R14 (best: ~207us GEMM).
// Occupancy 2, BM=128, BN=256, KC=32, 4-stage ring, (1,4,1) m-quad B-multicast.
// ===========================================================================
#define BM 128
#define BN 256
#define KC 32
#define NKT (F_DIM / KC)              // 128
#define A_TILE 8192
#define B_TILE 16384
#define STAGE_BYTES (A_TILE + B_TILE) // 24576
#define NSTAGE 4
#define SMEM_DATA 1024
#define GEMM_SMEM (SMEM_DATA + NSTAGE * STAGE_BYTES)   // 99328
#define CL 4
#define MC_MASK 0xF
#define TMEM_COLS 256

__global__ __launch_bounds__(256, 2) __cluster_dims__(1, CL, 1)
void gemm_tc_kernel(float* __restrict__ out, const float* __restrict__ b2)
{
#if HAS_BLACKWELL && defined(__CUDA_ARCH__)
    extern __shared__ char smem[];
    const uint32_t sbase = smem_u32(smem);
    const int tid  = threadIdx.x;
    const int warp = tid >> 5;
    const int lane = tid & 31;
    const int nb = blockIdx.x;        // 0..3
    const int n0 = nb * BN;
    const int m0 = blockIdx.y * BM;
    const uint32_t rank = ctarank();  // 0..3 within m-quad

    const uint32_t mb_full0 = sbase + 8;    // full[4]: +8..+39
    const uint32_t mb_free0 = sbase + 48;   // free[4]: +48..+79
    const uint32_t mb_done  = sbase + 88;

    if (warp == 0) {
        asm volatile("tcgen05.alloc.cta_group::1.sync.aligned.shared::cta.b32 [%0], %1;"
                     :: "r"(sbase), "r"((uint32_t)TMEM_COLS) : "memory");
    }
    __syncthreads();
    uint32_t tmem;
    asm volatile("ld.shared.b32 %0, [%1];" : "=r"(tmem) : "r"(sbase));
    if (warp == 0)
        asm volatile("tcgen05.relinquish_alloc_permit.cta_group::1.sync.aligned;");

    if (tid == 0) {
#pragma unroll
        for (int s = 0; s < NSTAGE; s++) {
            MBAR_INIT(mb_full0 + s * 8, 1);
            MBAR_INIT(mb_free0 + s * 8, CL);   // one multicast commit per quad CTA
        }
        MBAR_INIT(mb_done, 1);
    }
    __syncthreads();
    asm volatile("barrier.cluster.arrive.aligned;" ::: "memory");
    asm volatile("barrier.cluster.wait.aligned;"   ::: "memory");

    const char* Abase = (const char*)g_H + ((size_t)blockIdx.y * 128) * A_TILE;
    // B rows [nb*256, nb*256+255]: 512-row tile (nb>>1, kt), block (nb&1)*16384.
    const char* Bbase = (const char*)g_w2h + (((size_t)(nb >> 1) * 128) << 15)
                      + (size_t)(nb & 1) * 16384;
    const uint32_t idesc = (1u << 4) | ((BN / 8) << 17) | (8u << 24);  // F32 acc, N=256, M=128

    if (tid == 0) {
        // ---- producer ----
        for (int kn = 0; kn < NKT; kn++) {
            const int s = kn % NSTAGE;
            const int r = kn / NSTAGE;
            if (r >= 1) MBAR_WAIT(mb_free0 + s * 8, (r - 1) & 1);
            const uint32_t mb = mb_full0 + s * 8;
            const uint32_t sa = sbase + SMEM_DATA + s * STAGE_BYTES;
            const uint32_t sb = sa + A_TILE;
            MBAR_EXPECT_TX(mb, (uint32_t)STAGE_BYTES);  // A 8K + 4 x 4K B multicast slices
            BULK_G2S(sa, Abase + (size_t)kn * A_TILE, A_TILE, mb);
            BULK_G2S_MC(sb + rank * 4096,
                        Bbase + ((size_t)kn << 15) + rank * 4096,
                        4096, mb, MC_MASK);
        }
    } else if (warp == 1) {
        // ---- MMA issuer ----
        if (elect_one()) {
            for (int kt = 0; kt < NKT; kt++) {
                const int s = kt % NSTAGE;
                const int r = kt / NSTAGE;
                MBAR_WAIT(mb_full0 + s * 8, r & 1);
                const uint32_t sa = sbase + SMEM_DATA + s * STAGE_BYTES;
                const uint64_t adesc = make_desc64(sa);
                const uint64_t bdesc = make_desc64(sa + A_TILE);
#pragma unroll
                for (int k2 = 0; k2 < 2; k2++) {
                    mma_f16_ss(tmem, adesc + k2 * 2, bdesc + k2 * 2,
                               idesc, (kt > 0 || k2 > 0) ? 1u : 0u);
                }
                COMMIT_MC(mb_free0 + s * 8, MC_MASK);
            }
            COMMIT_LOCAL(mb_done);
        }
    }

    MBAR_WAIT(mb_done, 0);
    asm volatile("tcgen05.fence::after_thread_sync;" ::: "memory");

    // Epilogue: warp w covers rows (w&3)*32.., cols (w>>2)*128 + 0..127. Bias fused.
    {
        const int ch = warp >> 2;   // column half 0/1
        const uint32_t dbase = tmem + ch * 128;
        const size_t row = (size_t)(m0 + (warp & 3) * 32 + lane);
        float4* dst = (float4*)(out + row * E_DIM + n0 + ch * 128);
        const float* bp = b2 + n0 + ch * 128;
#pragma unroll
        for (int c0 = 0; c0 < 128; c0 += 32) {
            uint32_t r[32];
            TCGEN05_LD_X32(r, dbase + c0);
            asm volatile("tcgen05.wait::ld.sync.aligned;" ::: "memory");
#pragma unroll
            for (int q = 0; q < 8; q++) {
                float4 v;
                v.x = __uint_as_float(r[4 * q + 0]) + __ldg(bp + c0 + 4 * q + 0);
                v.y = __uint_as_float(r[4 * q + 1]) + __ldg(bp + c0 + 4 * q + 1);
                v.z = __uint_as_float(r[4 * q + 2]) + __ldg(bp + c0 + 4 * q + 2);
                v.w = __uint_as_float(r[4 * q + 3]) + __ldg(bp + c0 + 4 * q + 3);
                dst[(c0 >> 2) + q] = v;
            }
        }
        asm volatile("tcgen05.fence::before_thread_sync;" ::: "memory");
    }

    __syncthreads();
    if (tid == 0) {
#pragma unroll
        for (int s = 0; s < NSTAGE; s++) {
            asm volatile("mbarrier.inval.shared.b64 [%0];" :: "r"(mb_full0 + s * 8) : "memory");
            asm volatile("mbarrier.inval.shared.b64 [%0];" :: "r"(mb_free0 + s * 8) : "memory");
        }
        asm volatile("mbarrier.inval.shared.b64 [%0];" :: "r"(mb_done) : "memory");
    }
    __syncthreads();
    if (warp == 0) {
        asm volatile("tcgen05.dealloc.cta_group::1.sync.aligned.b32 %0, %1;"
                     :: "r"(tmem), "r"((uint32_t)TMEM_COLS));
    }
    asm volatile("barrier.cluster.arrive.aligned;" ::: "memory");
    asm volatile("barrier.cluster.wait.aligned;"   ::: "memory");
#endif  // HAS_BLACKWELL
}

// ===========================================================================
extern "C" void kernel_launch(void* const* d_in, const int* in_sizes, int n_in,
                              void* d_out, int out_size)
{
    const float* x     = (const float*)d_in[0];
    const float* theta = (const float*)d_in[1];
    const float* w1    = (const float*)d_in[2];
    const float* b1    = (const float*)d_in[3];
    const float* w2    = (const float*)d_in[4];
    const float* b2    = (const float*)d_in[5];
    float* out = (float*)d_out;

    // H blocks (1024) + w2-convert blocks (2048)
    prep_kernel<<<NBLK_H + (E_DIM * F_DIM / 8) / 256, 256>>>(x, theta, w1, b1, w2);

    cudaFuncSetAttribute(gemm_tc_kernel, cudaFuncAttributeMaxDynamicSharedMemorySize, GEMM_SMEM);
    dim3 gg(E_DIM / BN, M_TOK / BM);
    gemm_tc_kernel<<<gg, 256, GEMM_SMEM>>>(out, b2);
}